// round 1
// baseline (speedup 1.0000x reference)
#include <cuda_runtime.h>

// ---------------------------------------------------------------------------
// DirectGCNLayer on GB300 (sm_103a)
//
// Math: propagate is linear, so the 4 propagates in the reference collapse to 2:
//   Wc_in  = W_main_in  + W_shared ;  Wc_out = W_main_out + W_shared
//   H      = X @ [Wc_in | Wc_out]              (N x 128 fp32)
//   out[t] = C_in[t] *(sum_{e: tgt_in[e]=t } w_in[e] *H[src_in[e]][0:64]  + bc_in)
//          + C_out[t]*(sum_{e: tgt_out[e]=t} w_out[e]*H[src_out[e]][64:128]+ bc_out)
//
// Targets are SORTED -> CSR offsets via a boundary kernel -> atomic-free pull
// gather with one 64-thread group per target node (lane = channel).
// GEMM uses packed fma.rn.f32x2 (full-rate fp32 on sm_103a; scalar FFMA is
// half rate, rt_SMSP=2).
// ---------------------------------------------------------------------------

#define MAX_N 100000
#define MAX_E 1000000

typedef unsigned long long u64;

// scratch (device globals: no allocations allowed in kernel_launch)
__device__ float g_H[(size_t)MAX_N * 128];          // 51.2 MB
__device__ u64   g_Wp[128 * 128];                   // W packed as {w,w} f32x2 pairs
__device__ float g_bc[128];                         // combined biases [in | out]
__device__ int   g_off_in[MAX_N + 1];
__device__ int   g_off_out[MAX_N + 1];

__device__ __forceinline__ void ffma2(u64 &d, u64 a, u64 b) {
    asm("fma.rn.f32x2 %0, %1, %2, %0;" : "+l"(d) : "l"(a), "l"(b));
}
__device__ __forceinline__ u64 pack2(float lo, float hi) {
    u64 r; asm("mov.b64 %0, {%1, %2};" : "=l"(r) : "f"(lo), "f"(hi)); return r;
}
__device__ __forceinline__ void unpack2(float &lo, float &hi, u64 v) {
    asm("mov.b64 {%0, %1}, %2;" : "=f"(lo), "=f"(hi) : "l"(v));
}

// ---------------------------------------------------------------------------
// Combine weights/biases. W_* are [128 x 64] row-major. g_Wp[k*128 + j] holds
// the j-th output column of combined W at input k, duplicated into both f32x2
// lanes (so the GEMM inner loop needs no per-k broadcast packing for W).
// ---------------------------------------------------------------------------
__global__ void prep_kernel(const float* __restrict__ Wmi, const float* __restrict__ Wmo,
                            const float* __restrict__ Wsh,
                            const float* __restrict__ bmi, const float* __restrict__ bmo,
                            const float* __restrict__ bsi, const float* __restrict__ bso) {
    int i = blockIdx.x * blockDim.x + threadIdx.x;
    if (i < 128 * 64) {
        int k = i >> 6, j = i & 63;
        float win  = Wmi[i] + Wsh[i];
        float wout = Wmo[i] + Wsh[i];
        u64 ui = (u64)__float_as_uint(win);
        u64 uo = (u64)__float_as_uint(wout);
        g_Wp[k * 128 + j]      = ui | (ui << 32);
        g_Wp[k * 128 + 64 + j] = uo | (uo << 32);
    }
    if (i < 64) {
        g_bc[i]      = bmi[i] + bsi[i];
        g_bc[64 + i] = bmo[i] + bso[i];
    }
}

// ---------------------------------------------------------------------------
// CSR offsets from sorted target list: off[t] = first e with tgt[e] >= t.
// Thread e covers all t in (tgt[e-1], tgt[e]]; e==E covers the tail.
// ---------------------------------------------------------------------------
__global__ void offsets_kernel(const int* __restrict__ tgt, int E, int N, int which) {
    int e = blockIdx.x * blockDim.x + threadIdx.x;
    if (e > E) return;
    int* off = which ? g_off_out : g_off_in;
    int cur  = (e < E) ? tgt[e]     : N;
    int prev = (e > 0) ? tgt[e - 1] : -1;
    for (int t = prev + 1; t <= cur; ++t) off[t] = e;
}

// ---------------------------------------------------------------------------
// H = X @ Wc.  Tile: 64 nodes x 128 cols per 256-thread block, full K=128.
// X tile transposed into smem (Xs[k][node], padded stride) so 4 consecutive
// node values per k are one LDS.128. W read straight from L1-resident g_Wp
// (128 KB, fully cached). Thread (a=tid&15, b=tid>>4): nodes a*4..a*4+3,
// cols b*8..b*8+7 -> 16 f32x2 accumulators.
// ---------------------------------------------------------------------------
__global__ __launch_bounds__(256) void gemm_kernel(const float* __restrict__ X, int N) {
    __shared__ __align__(16) float Xs[128][68];
    int tid = threadIdx.x;
    int node0 = blockIdx.x * 64;

    // load 64x128 X tile, transposed
    {
        int r = tid >> 2;       // node row 0..63
        int q = tid & 3;        // k-quarter
        int n = node0 + r;
        const float4* xrow = (const float4*)(X + (size_t)n * 128);
        #pragma unroll
        for (int kk = 0; kk < 8; ++kk) {
            int k4 = q * 8 + kk;
            float4 v = (n < N) ? __ldg(&xrow[k4]) : make_float4(0.f, 0.f, 0.f, 0.f);
            int k = k4 * 4;
            Xs[k][r] = v.x; Xs[k + 1][r] = v.y; Xs[k + 2][r] = v.z; Xs[k + 3][r] = v.w;
        }
    }
    __syncthreads();

    int a = tid & 15;
    int b = tid >> 4;

    u64 acc01[8], acc23[8];
    #pragma unroll
    for (int j = 0; j < 8; ++j) { acc01[j] = 0ull; acc23[j] = 0ull; }

    #pragma unroll 8
    for (int k = 0; k < 128; ++k) {
        float4 xv = *(const float4*)&Xs[k][a * 4];
        u64 x01 = pack2(xv.x, xv.y);
        u64 x23 = pack2(xv.z, xv.w);
        const ulonglong2* wr = (const ulonglong2*)g_Wp + (k * 64 + b * 4);
        ulonglong2 w0 = __ldg(&wr[0]);
        ulonglong2 w1 = __ldg(&wr[1]);
        ulonglong2 w2 = __ldg(&wr[2]);
        ulonglong2 w3 = __ldg(&wr[3]);
        ffma2(acc01[0], x01, w0.x); ffma2(acc23[0], x23, w0.x);
        ffma2(acc01[1], x01, w0.y); ffma2(acc23[1], x23, w0.y);
        ffma2(acc01[2], x01, w1.x); ffma2(acc23[2], x23, w1.x);
        ffma2(acc01[3], x01, w1.y); ffma2(acc23[3], x23, w1.y);
        ffma2(acc01[4], x01, w2.x); ffma2(acc23[4], x23, w2.x);
        ffma2(acc01[5], x01, w2.y); ffma2(acc23[5], x23, w2.y);
        ffma2(acc01[6], x01, w3.x); ffma2(acc23[6], x23, w3.x);
        ffma2(acc01[7], x01, w3.y); ffma2(acc23[7], x23, w3.y);
    }

    float v0[8], v1[8], v2[8], v3[8];
    #pragma unroll
    for (int j = 0; j < 8; ++j) {
        unpack2(v0[j], v1[j], acc01[j]);
        unpack2(v2[j], v3[j], acc23[j]);
    }
    int nb = node0 + a * 4;
    float* Hp = g_H + (size_t)nb * 128 + b * 8;
    if (nb + 0 < N) {
        *(float4*)(Hp)           = make_float4(v0[0], v0[1], v0[2], v0[3]);
        *(float4*)(Hp + 4)       = make_float4(v0[4], v0[5], v0[6], v0[7]);
    }
    if (nb + 1 < N) {
        *(float4*)(Hp + 128)     = make_float4(v1[0], v1[1], v1[2], v1[3]);
        *(float4*)(Hp + 132)     = make_float4(v1[4], v1[5], v1[6], v1[7]);
    }
    if (nb + 2 < N) {
        *(float4*)(Hp + 256)     = make_float4(v2[0], v2[1], v2[2], v2[3]);
        *(float4*)(Hp + 260)     = make_float4(v2[4], v2[5], v2[6], v2[7]);
    }
    if (nb + 3 < N) {
        *(float4*)(Hp + 384)     = make_float4(v3[0], v3[1], v3[2], v3[3]);
        *(float4*)(Hp + 388)     = make_float4(v3[4], v3[5], v3[6], v3[7]);
    }
}

// ---------------------------------------------------------------------------
// Pull gather: 64-thread group per target node, lane = channel. No atomics,
// no syncs, no shared memory. src/w loads are lane-uniform (broadcast); the
// H-row gather is 2 coalesced 128B lines per edge per path, L2-resident.
// ---------------------------------------------------------------------------
__global__ __launch_bounds__(256) void gather_kernel(
        const int* __restrict__ src_in,  const float* __restrict__ w_in,
        const int* __restrict__ src_out, const float* __restrict__ w_out,
        const float* __restrict__ Cin,   const float* __restrict__ Cout,
        float* __restrict__ out, int N) {
    int gid = blockIdx.x * blockDim.x + threadIdx.x;
    int t = gid >> 6;
    if (t >= N) return;
    int c = gid & 63;

    float acc_in = 0.f;
    {
        int lo = g_off_in[t], hi = g_off_in[t + 1];
        const float* Hp = g_H + c;
        int e = lo;
        for (; e + 1 < hi; e += 2) {
            int   s0  = __ldg(&src_in[e]);
            int   s1  = __ldg(&src_in[e + 1]);
            float ww0 = __ldg(&w_in[e]);
            float ww1 = __ldg(&w_in[e + 1]);
            acc_in += ww0 * Hp[(size_t)s0 * 128];
            acc_in += ww1 * Hp[(size_t)s1 * 128];
        }
        if (e < hi)
            acc_in += __ldg(&w_in[e]) * Hp[(size_t)__ldg(&src_in[e]) * 128];
    }

    float acc_out = 0.f;
    {
        int lo = g_off_out[t], hi = g_off_out[t + 1];
        const float* Hp = g_H + 64 + c;
        int e = lo;
        for (; e + 1 < hi; e += 2) {
            int   s0  = __ldg(&src_out[e]);
            int   s1  = __ldg(&src_out[e + 1]);
            float ww0 = __ldg(&w_out[e]);
            float ww1 = __ldg(&w_out[e + 1]);
            acc_out += ww0 * Hp[(size_t)s0 * 128];
            acc_out += ww1 * Hp[(size_t)s1 * 128];
        }
        if (e < hi)
            acc_out += __ldg(&w_out[e]) * Hp[(size_t)__ldg(&src_out[e]) * 128];
    }

    float r = Cin[t] * (acc_in + g_bc[c]) + Cout[t] * (acc_out + g_bc[64 + c]);
    out[(size_t)t * 64 + c] = r;
}

// ---------------------------------------------------------------------------
// Launch. Inputs (metadata order): x, W_main_in, W_main_out, W_shared,
// bias_main_in, bias_main_out, bias_shared_in, bias_shared_out,
// C_in_vec, C_out_vec, edge_index_in(2,E), edge_weight_in,
// edge_index_out(2,E), edge_weight_out.
// ---------------------------------------------------------------------------
extern "C" void kernel_launch(void* const* d_in, const int* in_sizes, int n_in,
                              void* d_out, int out_size) {
    const float* x    = (const float*)d_in[0];
    const float* Wmi  = (const float*)d_in[1];
    const float* Wmo  = (const float*)d_in[2];
    const float* Wsh  = (const float*)d_in[3];
    const float* bmi  = (const float*)d_in[4];
    const float* bmo  = (const float*)d_in[5];
    const float* bsi  = (const float*)d_in[6];
    const float* bso  = (const float*)d_in[7];
    const float* Cin  = (const float*)d_in[8];
    const float* Cout = (const float*)d_in[9];
    const int*   ei_in  = (const int*)d_in[10];
    const float* ew_in  = (const float*)d_in[11];
    const int*   ei_out = (const int*)d_in[12];
    const float* ew_out = (const float*)d_in[13];

    int N    = in_sizes[0] / 128;
    int Ein  = in_sizes[10] / 2;
    int Eout = in_sizes[12] / 2;
    float* out = (float*)d_out;

    prep_kernel<<<32, 256>>>(Wmi, Wmo, Wsh, bmi, bmo, bsi, bso);
    offsets_kernel<<<(Ein  + 1 + 255) / 256, 256>>>(ei_in  + Ein,  Ein,  N, 0);
    offsets_kernel<<<(Eout + 1 + 255) / 256, 256>>>(ei_out + Eout, Eout, N, 1);
    gemm_kernel<<<(N + 63) / 64, 256>>>(x, N);
    gather_kernel<<<((size_t)N * 64 + 255) / 256, 256>>>(
        ei_in, ew_in, ei_out, ew_out, Cin, Cout, out, N);
}

// round 2
// speedup vs baseline: 1.2510x; 1.2510x over previous
#include <cuda_runtime.h>

// ---------------------------------------------------------------------------
// DirectGCNLayer on GB300 (sm_103a)
//
//   Wc_in  = W_main_in  + W_shared ;  Wc_out = W_main_out + W_shared
//   H      = X @ [Wc_in | Wc_out]              (N x 128 fp32)
//   out[t] = C_in[t] *(sum_in  w*H[src][0:64]   + bc_in)
//          + C_out[t]*(sum_out w*H[src][64:128] + bc_out)
//
// R2: GEMM rebuilt to be FFMA2-issue-bound instead of L1-bound:
//   - 8 nodes x 8 cols per thread (128x128 tile / 256 threads)
//   - adjacent-node pairs -> LDS.64 IS the packed f32x2 operand (no packs,
//     conflict-free 128B-contiguous shared reads)
//   - per k: 4 LDS.64 + 4 LDG.128 (dup-packed W, L1-resident) + 32 FFMA2
// ---------------------------------------------------------------------------

#define MAX_N 100000
#define MAX_E 1000000

typedef unsigned long long u64;

__device__ float g_H[(size_t)MAX_N * 128];          // 51.2 MB
__device__ u64   g_Wp[128 * 128];                   // W as {w,w} f32x2 pairs
__device__ float g_bc[128];                         // combined biases [in|out]
__device__ int   g_off_in[MAX_N + 1];
__device__ int   g_off_out[MAX_N + 1];

__device__ __forceinline__ void ffma2(u64 &d, u64 a, u64 b) {
    asm("fma.rn.f32x2 %0, %1, %2, %0;" : "+l"(d) : "l"(a), "l"(b));
}
__device__ __forceinline__ void unpack2(float &lo, float &hi, u64 v) {
    asm("mov.b64 {%0, %1}, %2;" : "=f"(lo), "=f"(hi) : "l"(v));
}

// ---------------------------------------------------------------------------
// Combine weights/biases. W_* are [128 x 64] row-major (k-major). g_Wp[k*128+j]
// holds combined-W col j at input k, duplicated into both f32x2 lanes.
// j in [0,64): in-path; j in [64,128): out-path.
// ---------------------------------------------------------------------------
__global__ void prep_kernel(const float* __restrict__ Wmi, const float* __restrict__ Wmo,
                            const float* __restrict__ Wsh,
                            const float* __restrict__ bmi, const float* __restrict__ bmo,
                            const float* __restrict__ bsi, const float* __restrict__ bso) {
    int i = blockIdx.x * blockDim.x + threadIdx.x;
    if (i < 128 * 64) {
        int k = i >> 6, j = i & 63;
        float win  = Wmi[i] + Wsh[i];
        float wout = Wmo[i] + Wsh[i];
        u64 ui = (u64)__float_as_uint(win);
        u64 uo = (u64)__float_as_uint(wout);
        g_Wp[k * 128 + j]      = ui | (ui << 32);
        g_Wp[k * 128 + 64 + j] = uo | (uo << 32);
    }
    if (i < 64) {
        g_bc[i]      = bmi[i] + bsi[i];
        g_bc[64 + i] = bmo[i] + bso[i];
    }
}

// ---------------------------------------------------------------------------
// CSR offsets from sorted target list: off[t] = first e with tgt[e] >= t.
// ---------------------------------------------------------------------------
__global__ void offsets_kernel(const int* __restrict__ tgt, int E, int N, int which) {
    int e = blockIdx.x * blockDim.x + threadIdx.x;
    if (e > E) return;
    int* off = which ? g_off_out : g_off_in;
    int cur  = (e < E) ? tgt[e]     : N;
    int prev = (e > 0) ? tgt[e - 1] : -1;
    for (int t = prev + 1; t <= cur; ++t) off[t] = e;
}

// ---------------------------------------------------------------------------
// H = X @ Wc.  128 nodes x 128 cols per 256-thread block.
// Thread (a=tid&15, b=tid>>4): node pairs {2a,2a+1}+32*np (np=0..3),
// cols b*8..b*8+7. Per k: 4x LDS.64 (x pairs, contiguous -> conflict-free),
// 4x LDG.128 (W dup-pairs, broadcast within half-warp, L1-hit),
// 32x fma.rn.f32x2.
// ---------------------------------------------------------------------------
__global__ __launch_bounds__(256, 2) void gemm_kernel(const float* __restrict__ X, int N) {
    __shared__ __align__(16) float Xs[128][130];   // [k][node], stride even for LDS.64
    int tid = threadIdx.x;
    int node0 = blockIdx.x * 128;

    // Load 128x128 X tile transposed. 2 threads/row; interleaved k4 (=2*kk+h)
    // de-conflicts the transposed scalar stores.
    {
        int r = tid >> 1;          // node row 0..127
        int h = tid & 1;
        int n = node0 + r;
        const float4* xrow = (const float4*)(X + (size_t)n * 128);
        #pragma unroll
        for (int kk = 0; kk < 16; ++kk) {
            int k4 = kk * 2 + h;
            float4 v = (n < N) ? __ldg(&xrow[k4]) : make_float4(0.f, 0.f, 0.f, 0.f);
            int k = k4 * 4;
            Xs[k][r] = v.x; Xs[k + 1][r] = v.y; Xs[k + 2][r] = v.z; Xs[k + 3][r] = v.w;
        }
    }
    __syncthreads();

    int a = tid & 15;      // node pair base 2a
    int b = tid >> 4;      // col group: cols b*8..b*8+7

    u64 acc[4][8];
    #pragma unroll
    for (int i = 0; i < 4; ++i)
        #pragma unroll
        for (int j = 0; j < 8; ++j) acc[i][j] = 0ull;

    const u64* wbase = g_Wp + b * 8;
    int a2 = a * 2;

    #pragma unroll 2
    for (int k = 0; k < 128; ++k) {
        u64 x0 = *(const u64*)&Xs[k][a2];         // {x[2a],   x[2a+1]}
        u64 x1 = *(const u64*)&Xs[k][a2 + 32];
        u64 x2 = *(const u64*)&Xs[k][a2 + 64];
        u64 x3 = *(const u64*)&Xs[k][a2 + 96];
        const ulonglong2* wr = (const ulonglong2*)(wbase + (size_t)k * 128);
        ulonglong2 w0 = __ldg(&wr[0]);            // cols b*8+0, b*8+1 (dup pairs)
        ulonglong2 w1 = __ldg(&wr[1]);
        ulonglong2 w2 = __ldg(&wr[2]);
        ulonglong2 w3 = __ldg(&wr[3]);
        ffma2(acc[0][0], x0, w0.x); ffma2(acc[0][1], x0, w0.y);
        ffma2(acc[0][2], x0, w1.x); ffma2(acc[0][3], x0, w1.y);
        ffma2(acc[0][4], x0, w2.x); ffma2(acc[0][5], x0, w2.y);
        ffma2(acc[0][6], x0, w3.x); ffma2(acc[0][7], x0, w3.y);
        ffma2(acc[1][0], x1, w0.x); ffma2(acc[1][1], x1, w0.y);
        ffma2(acc[1][2], x1, w1.x); ffma2(acc[1][3], x1, w1.y);
        ffma2(acc[1][4], x1, w2.x); ffma2(acc[1][5], x1, w2.y);
        ffma2(acc[1][6], x1, w3.x); ffma2(acc[1][7], x1, w3.y);
        ffma2(acc[2][0], x2, w0.x); ffma2(acc[2][1], x2, w0.y);
        ffma2(acc[2][2], x2, w1.x); ffma2(acc[2][3], x2, w1.y);
        ffma2(acc[2][4], x2, w2.x); ffma2(acc[2][5], x2, w2.y);
        ffma2(acc[2][6], x2, w3.x); ffma2(acc[2][7], x2, w3.y);
        ffma2(acc[3][0], x3, w0.x); ffma2(acc[3][1], x3, w0.y);
        ffma2(acc[3][2], x3, w1.x); ffma2(acc[3][3], x3, w1.y);
        ffma2(acc[3][4], x3, w2.x); ffma2(acc[3][5], x3, w2.y);
        ffma2(acc[3][6], x3, w3.x); ffma2(acc[3][7], x3, w3.y);
    }

    #pragma unroll
    for (int np = 0; np < 4; ++np) {
        int n = node0 + np * 32 + a2;
        float lo[8], hi[8];
        #pragma unroll
        for (int c = 0; c < 8; ++c) unpack2(lo[c], hi[c], acc[np][c]);
        float* Hp = g_H + (size_t)n * 128 + b * 8;
        if (n < N) {
            *(float4*)(Hp)     = make_float4(lo[0], lo[1], lo[2], lo[3]);
            *(float4*)(Hp + 4) = make_float4(lo[4], lo[5], lo[6], lo[7]);
        }
        if (n + 1 < N) {
            *(float4*)(Hp + 128) = make_float4(hi[0], hi[1], hi[2], hi[3]);
            *(float4*)(Hp + 132) = make_float4(hi[4], hi[5], hi[6], hi[7]);
        }
    }
}

// ---------------------------------------------------------------------------
// Pull gather: 64-thread group per target node, lane = channel. Atomic-free,
// L2-resident H rows (2 coalesced 128B lines per edge per path).
// ---------------------------------------------------------------------------
__global__ __launch_bounds__(256) void gather_kernel(
        const int* __restrict__ src_in,  const float* __restrict__ w_in,
        const int* __restrict__ src_out, const float* __restrict__ w_out,
        const float* __restrict__ Cin,   const float* __restrict__ Cout,
        float* __restrict__ out, int N) {
    int gid = blockIdx.x * blockDim.x + threadIdx.x;
    int t = gid >> 6;
    if (t >= N) return;
    int c = gid & 63;

    float acc_in = 0.f;
    {
        int lo = g_off_in[t], hi = g_off_in[t + 1];
        const float* Hp = g_H + c;
        int e = lo;
        for (; e + 1 < hi; e += 2) {
            int   s0  = __ldg(&src_in[e]);
            int   s1  = __ldg(&src_in[e + 1]);
            float ww0 = __ldg(&w_in[e]);
            float ww1 = __ldg(&w_in[e + 1]);
            acc_in += ww0 * Hp[(size_t)s0 * 128];
            acc_in += ww1 * Hp[(size_t)s1 * 128];
        }
        if (e < hi)
            acc_in += __ldg(&w_in[e]) * Hp[(size_t)__ldg(&src_in[e]) * 128];
    }

    float acc_out = 0.f;
    {
        int lo = g_off_out[t], hi = g_off_out[t + 1];
        const float* Hp = g_H + 64 + c;
        int e = lo;
        for (; e + 1 < hi; e += 2) {
            int   s0  = __ldg(&src_out[e]);
            int   s1  = __ldg(&src_out[e + 1]);
            float ww0 = __ldg(&w_out[e]);
            float ww1 = __ldg(&w_out[e + 1]);
            acc_out += ww0 * Hp[(size_t)s0 * 128];
            acc_out += ww1 * Hp[(size_t)s1 * 128];
        }
        if (e < hi)
            acc_out += __ldg(&w_out[e]) * Hp[(size_t)__ldg(&src_out[e]) * 128];
    }

    float r = Cin[t] * (acc_in + g_bc[c]) + Cout[t] * (acc_out + g_bc[64 + c]);
    out[(size_t)t * 64 + c] = r;
}

// ---------------------------------------------------------------------------
extern "C" void kernel_launch(void* const* d_in, const int* in_sizes, int n_in,
                              void* d_out, int out_size) {
    const float* x    = (const float*)d_in[0];
    const float* Wmi  = (const float*)d_in[1];
    const float* Wmo  = (const float*)d_in[2];
    const float* Wsh  = (const float*)d_in[3];
    const float* bmi  = (const float*)d_in[4];
    const float* bmo  = (const float*)d_in[5];
    const float* bsi  = (const float*)d_in[6];
    const float* bso  = (const float*)d_in[7];
    const float* Cin  = (const float*)d_in[8];
    const float* Cout = (const float*)d_in[9];
    const int*   ei_in  = (const int*)d_in[10];
    const float* ew_in  = (const float*)d_in[11];
    const int*   ei_out = (const int*)d_in[12];
    const float* ew_out = (const float*)d_in[13];

    int N    = in_sizes[0] / 128;
    int Ein  = in_sizes[10] / 2;
    int Eout = in_sizes[12] / 2;
    float* out = (float*)d_out;

    prep_kernel<<<32, 256>>>(Wmi, Wmo, Wsh, bmi, bmo, bsi, bso);
    offsets_kernel<<<(Ein  + 1 + 255) / 256, 256>>>(ei_in  + Ein,  Ein,  N, 0);
    offsets_kernel<<<(Eout + 1 + 255) / 256, 256>>>(ei_out + Eout, Eout, N, 1);
    gemm_kernel<<<(N + 127) / 128, 256>>>(x, N);
    gather_kernel<<<((size_t)N * 64 + 255) / 256, 256>>>(
        ei_in, ew_in, ei_out, ew_out, Cin, Cout, out, N);
}

// round 5
// speedup vs baseline: 1.5759x; 1.2597x over previous
#include <cuda_runtime.h>

// ---------------------------------------------------------------------------
// DirectGCNLayer on GB300 (sm_103a)
//
//   Wc_in  = W_main_in  + W_shared ;  Wc_out = W_main_out + W_shared
//   H      = X @ [Wc_in | Wc_out]              (N x 128 fp32)
//   out[t] = C_in[t] *(sum_in  w*H[src][0:64]   + bc_in)
//          + C_out[t]*(sum_out w*H[src][64:128] + bc_out)
//
// R3:
//  - GEMM: 16 nodes x 8 cols per thread (128-thread block, 128x128 tile).
//    Per k: 8 LDS.64 + 4 LDG.128 + 64 FFMA2 -> FFMA2-issue-bound (~45us floor).
//  - Gather: warp-per-node, lane = channel pair (2l,2l+1), LDG.64 H reads,
//    f32x2 accumulate, unroll 4 for MLP.
// ---------------------------------------------------------------------------

#define MAX_N 100000
#define MAX_E 1000000

typedef unsigned long long u64;

__device__ float g_H[(size_t)MAX_N * 128];          // 51.2 MB
__device__ u64   g_Wp[128 * 128];                   // W as {w,w} f32x2 pairs
__device__ float g_bc[128];                         // combined biases [in|out]
__device__ int   g_off_in[MAX_N + 1];
__device__ int   g_off_out[MAX_N + 1];

__device__ __forceinline__ void ffma2(u64 &d, u64 a, u64 b) {
    asm("fma.rn.f32x2 %0, %1, %2, %0;" : "+l"(d) : "l"(a), "l"(b));
}
__device__ __forceinline__ u64 pack2(float lo, float hi) {
    u64 r; asm("mov.b64 %0, {%1, %2};" : "=l"(r) : "f"(lo), "f"(hi)); return r;
}
__device__ __forceinline__ void unpack2(float &lo, float &hi, u64 v) {
    asm("mov.b64 {%0, %1}, %2;" : "=f"(lo), "=f"(hi) : "l"(v));
}

// ---------------------------------------------------------------------------
// Combine weights/biases. W_* are [128 x 64] row-major (k-major). g_Wp[k*128+j]
// holds combined-W col j at input k, duplicated into both f32x2 lanes.
// ---------------------------------------------------------------------------
__global__ void prep_kernel(const float* __restrict__ Wmi, const float* __restrict__ Wmo,
                            const float* __restrict__ Wsh,
                            const float* __restrict__ bmi, const float* __restrict__ bmo,
                            const float* __restrict__ bsi, const float* __restrict__ bso) {
    int i = blockIdx.x * blockDim.x + threadIdx.x;
    if (i < 128 * 64) {
        int k = i >> 6, j = i & 63;
        float win  = Wmi[i] + Wsh[i];
        float wout = Wmo[i] + Wsh[i];
        u64 ui = (u64)__float_as_uint(win);
        u64 uo = (u64)__float_as_uint(wout);
        g_Wp[k * 128 + j]      = ui | (ui << 32);
        g_Wp[k * 128 + 64 + j] = uo | (uo << 32);
    }
    if (i < 64) {
        g_bc[i]      = bmi[i] + bsi[i];
        g_bc[64 + i] = bmo[i] + bso[i];
    }
}

// ---------------------------------------------------------------------------
// CSR offsets for BOTH sorted target lists in one launch.
// off[t] = first e with tgt[e] >= t.
// ---------------------------------------------------------------------------
__global__ void offsets_kernel(const int* __restrict__ tgt_in,  int Ein,
                               const int* __restrict__ tgt_out, int Eout, int N) {
    int e = blockIdx.x * blockDim.x + threadIdx.x;
    if (e <= Ein) {
        int cur  = (e < Ein) ? tgt_in[e]     : N;
        int prev = (e > 0)   ? tgt_in[e - 1] : -1;
        for (int t = prev + 1; t <= cur; ++t) g_off_in[t] = e;
    }
    if (e <= Eout) {
        int cur  = (e < Eout) ? tgt_out[e]     : N;
        int prev = (e > 0)    ? tgt_out[e - 1] : -1;
        for (int t = prev + 1; t <= cur; ++t) g_off_out[t] = e;
    }
}

// ---------------------------------------------------------------------------
// H = X @ Wc.  128 nodes x 128 cols per 128-thread block.
// Thread (a=tid&7, b=tid>>3): node pairs {2a+16i : i=0..7}, cols b*8..b*8+7.
// Per k: 8x LDS.64 (X pairs, conflict-free) + 4x LDG.128 (dup-packed W,
// L1-resident) + 64x fma.rn.f32x2.
// ---------------------------------------------------------------------------
__global__ __launch_bounds__(128, 2) void gemm_kernel(const float* __restrict__ X, int N) {
    __shared__ __align__(16) float Xs[128][130];   // [k][node]
    int tid = threadIdx.x;
    int node0 = blockIdx.x * 128;

    // Load 128x128 X tile transposed; thread = one node row.
    {
        int n = node0 + tid;
        const float4* xrow = (const float4*)(X + (size_t)n * 128);
        #pragma unroll
        for (int k4 = 0; k4 < 32; ++k4) {
            float4 v = (n < N) ? __ldg(&xrow[k4]) : make_float4(0.f, 0.f, 0.f, 0.f);
            int k = k4 * 4;
            Xs[k][tid] = v.x; Xs[k + 1][tid] = v.y;
            Xs[k + 2][tid] = v.z; Xs[k + 3][tid] = v.w;
        }
    }
    __syncthreads();

    int a = tid & 7;       // node-pair base 2a, stride 16
    int b = tid >> 3;      // col group b*8 (b = 0..15)
    int a2 = a * 2;

    u64 acc[8][8];
    #pragma unroll
    for (int i = 0; i < 8; ++i)
        #pragma unroll
        for (int j = 0; j < 8; ++j) acc[i][j] = 0ull;

    const u64* wbase = g_Wp + b * 8;

    #pragma unroll 2
    for (int k = 0; k < 128; ++k) {
        u64 x[8];
        #pragma unroll
        for (int i = 0; i < 8; ++i)
            x[i] = *(const u64*)&Xs[k][a2 + 16 * i];
        const ulonglong2* wr = (const ulonglong2*)(wbase + (size_t)k * 128);
        ulonglong2 wq0 = __ldg(&wr[0]);
        ulonglong2 wq1 = __ldg(&wr[1]);
        ulonglong2 wq2 = __ldg(&wr[2]);
        ulonglong2 wq3 = __ldg(&wr[3]);
        u64 w[8] = {wq0.x, wq0.y, wq1.x, wq1.y, wq2.x, wq2.y, wq3.x, wq3.y};
        #pragma unroll
        for (int i = 0; i < 8; ++i)
            #pragma unroll
            for (int j = 0; j < 8; ++j)
                ffma2(acc[i][j], x[i], w[j]);
    }

    #pragma unroll
    for (int i = 0; i < 8; ++i) {
        int n = node0 + a2 + 16 * i;
        float lo[8], hi[8];
        #pragma unroll
        for (int j = 0; j < 8; ++j) unpack2(lo[j], hi[j], acc[i][j]);
        float* Hp = g_H + (size_t)n * 128 + b * 8;
        if (n < N) {
            *(float4*)(Hp)     = make_float4(lo[0], lo[1], lo[2], lo[3]);
            *(float4*)(Hp + 4) = make_float4(lo[4], lo[5], lo[6], lo[7]);
        }
        if (n + 1 < N) {
            *(float4*)(Hp + 128) = make_float4(hi[0], hi[1], hi[2], hi[3]);
            *(float4*)(Hp + 132) = make_float4(hi[4], hi[5], hi[6], hi[7]);
        }
    }
}

// ---------------------------------------------------------------------------
// Pull gather: ONE WARP per target node. Lane l owns channel pair (2l, 2l+1)
// of each path. H row read = 1 LDG.64/lane (256 B/warp, 2 lines, L2-resident).
// f32x2 accumulate; unroll 4 for MLP.
// ---------------------------------------------------------------------------
__global__ __launch_bounds__(256) void gather_kernel(
        const int* __restrict__ src_in,  const float* __restrict__ w_in,
        const int* __restrict__ src_out, const float* __restrict__ w_out,
        const float* __restrict__ Cin,   const float* __restrict__ Cout,
        float* __restrict__ out, int N) {
    int gid = blockIdx.x * blockDim.x + threadIdx.x;
    int t = gid >> 5;
    if (t >= N) return;
    int l2 = (gid & 31) * 2;           // channel pair (l2, l2+1)

    u64 acc_in = 0ull;
    {
        int lo = g_off_in[t], hi = g_off_in[t + 1];
        const u64* Hp = (const u64*)(g_H + l2);   // stride 64 u64 per node
        int e = lo;
        for (; e + 3 < hi; e += 4) {
            int   s0 = __ldg(&src_in[e]),     s1 = __ldg(&src_in[e + 1]);
            int   s2 = __ldg(&src_in[e + 2]), s3 = __ldg(&src_in[e + 3]);
            float f0 = __ldg(&w_in[e]),       f1 = __ldg(&w_in[e + 1]);
            float f2 = __ldg(&w_in[e + 2]),   f3 = __ldg(&w_in[e + 3]);
            u64 h0 = __ldg(&Hp[(size_t)s0 * 64]);
            u64 h1 = __ldg(&Hp[(size_t)s1 * 64]);
            u64 h2 = __ldg(&Hp[(size_t)s2 * 64]);
            u64 h3 = __ldg(&Hp[(size_t)s3 * 64]);
            ffma2(acc_in, pack2(f0, f0), h0);
            ffma2(acc_in, pack2(f1, f1), h1);
            ffma2(acc_in, pack2(f2, f2), h2);
            ffma2(acc_in, pack2(f3, f3), h3);
        }
        for (; e < hi; ++e) {
            float f = __ldg(&w_in[e]);
            u64 h = __ldg(&Hp[(size_t)__ldg(&src_in[e]) * 64]);
            ffma2(acc_in, pack2(f, f), h);
        }
    }

    u64 acc_out = 0ull;
    {
        int lo = g_off_out[t], hi = g_off_out[t + 1];
        const u64* Hp = (const u64*)(g_H + 64 + l2);
        int e = lo;
        for (; e + 3 < hi; e += 4) {
            int   s0 = __ldg(&src_out[e]),     s1 = __ldg(&src_out[e + 1]);
            int   s2 = __ldg(&src_out[e + 2]), s3 = __ldg(&src_out[e + 3]);
            float f0 = __ldg(&w_out[e]),       f1 = __ldg(&w_out[e + 1]);
            float f2 = __ldg(&w_out[e + 2]),   f3 = __ldg(&w_out[e + 3]);
            u64 h0 = __ldg(&Hp[(size_t)s0 * 64]);
            u64 h1 = __ldg(&Hp[(size_t)s1 * 64]);
            u64 h2 = __ldg(&Hp[(size_t)s2 * 64]);
            u64 h3 = __ldg(&Hp[(size_t)s3 * 64]);
            ffma2(acc_out, pack2(f0, f0), h0);
            ffma2(acc_out, pack2(f1, f1), h1);
            ffma2(acc_out, pack2(f2, f2), h2);
            ffma2(acc_out, pack2(f3, f3), h3);
        }
        for (; e < hi; ++e) {
            float f = __ldg(&w_out[e]);
            u64 h = __ldg(&Hp[(size_t)__ldg(&src_out[e]) * 64]);
            ffma2(acc_out, pack2(f, f), h);
        }
    }

    float ai, aj, oi, oj;
    unpack2(ai, aj, acc_in);
    unpack2(oi, oj, acc_out);
    float ci = __ldg(&Cin[t]), co = __ldg(&Cout[t]);
    float2 r;
    r.x = ci * (ai + g_bc[l2])     + co * (oi + g_bc[64 + l2]);
    r.y = ci * (aj + g_bc[l2 + 1]) + co * (oj + g_bc[65 + l2]);
    *(float2*)&out[(size_t)t * 64 + l2] = r;
}

// ---------------------------------------------------------------------------
extern "C" void kernel_launch(void* const* d_in, const int* in_sizes, int n_in,
                              void* d_out, int out_size) {
    const float* x    = (const float*)d_in[0];
    const float* Wmi  = (const float*)d_in[1];
    const float* Wmo  = (const float*)d_in[2];
    const float* Wsh  = (const float*)d_in[3];
    const float* bmi  = (const float*)d_in[4];
    const float* bmo  = (const float*)d_in[5];
    const float* bsi  = (const float*)d_in[6];
    const float* bso  = (const float*)d_in[7];
    const float* Cin  = (const float*)d_in[8];
    const float* Cout = (const float*)d_in[9];
    const int*   ei_in  = (const int*)d_in[10];
    const float* ew_in  = (const float*)d_in[11];
    const int*   ei_out = (const int*)d_in[12];
    const float* ew_out = (const float*)d_in[13];

    int N    = in_sizes[0] / 128;
    int Ein  = in_sizes[10] / 2;
    int Eout = in_sizes[12] / 2;
    float* out = (float*)d_out;

    int Emax = (Ein > Eout ? Ein : Eout);

    prep_kernel<<<32, 256>>>(Wmi, Wmo, Wsh, bmi, bmo, bsi, bso);
    offsets_kernel<<<(Emax + 1 + 255) / 256, 256>>>(ei_in + Ein, Ein,
                                                    ei_out + Eout, Eout, N);
    gemm_kernel<<<(N + 127) / 128, 128>>>(x, N);
    gather_kernel<<<((size_t)N * 32 + 255) / 256, 256>>>(
        ei_in, ew_in, ei_out, ew_out, Cin, Cout, out, N);
}

// round 9
// speedup vs baseline: 2.1698x; 1.3769x over previous
#include <cuda_runtime.h>
#include <cuda_bf16.h>
#include <cstdint>

// ---------------------------------------------------------------------------
// DirectGCNLayer on GB300 (sm_103a) — R8
//
//   Wc_in  = W_main_in  + W_shared ;  Wc_out = W_main_out + W_shared
//   H      = X @ [Wc_in | Wc_out]              (N x 128 fp32)
//   out[t] = C_in[t] *(sum_in  w*H[src][0:64]   + bc_in)
//          + C_out[t]*(sum_out w*H[src][64:128] + bc_out)
//
// R8: harness PTX target is plain sm_103 (no 'a') -> tcgen05 rejected by
// ptxas. Use the legacy tensor-core path instead: mma.sync.m16n8k16 bf16
// (HMMA) with bf16 hi/lo split, 3 passes, fp32 accumulators:
//     H = Xhi@Bhi + Xhi@Blo + Xlo@Bhi
// 128x128x128 tile/CTA, 8 warps (4 row x 2 col), ldmatrix feeds from padded
// SMEM (stride 272B -> conflict-free 8-row phases).
// Gather: warp-per-node pull (atomic-free, CSR from sorted targets).
// ---------------------------------------------------------------------------

#define MAX_N 100000

typedef unsigned long long u64;
typedef unsigned int u32;

// padded bf16 tile: 128 rows x 136 cols (272 B row stride)
#define TSTRIDE 272
#define TILE_BYTES (128 * TSTRIDE)     // 34816

__device__ float g_H[(size_t)MAX_N * 128];          // 51.2 MB
__device__ float g_bc[128];                         // combined biases [in|out]
__device__ int   g_off_in[MAX_N + 1];
__device__ int   g_off_out[MAX_N + 1];
__device__ __align__(16) unsigned char g_Bhi[TILE_BYTES]; // B=Wc^T bf16 hi, padded
__device__ __align__(16) unsigned char g_Blo[TILE_BYTES]; // B=Wc^T bf16 lo, padded

// ---- helpers ---------------------------------------------------------------
__device__ __forceinline__ void ffma2(u64 &d, u64 a, u64 b) {
    asm("fma.rn.f32x2 %0, %1, %2, %0;" : "+l"(d) : "l"(a), "l"(b));
}
__device__ __forceinline__ u64 pack2(float lo, float hi) {
    u64 r; asm("mov.b64 %0, {%1, %2};" : "=l"(r) : "f"(lo), "f"(hi)); return r;
}
__device__ __forceinline__ void unpack2(float &lo, float &hi, u64 v) {
    asm("mov.b64 {%0, %1}, %2;" : "=f"(lo), "=f"(hi) : "l"(v));
}
__device__ __forceinline__ u32 smem_u32(const void* p) {
    u32 a; asm("{ .reg .u64 t; cvta.to.shared.u64 t, %1; cvt.u32.u64 %0, t; }"
               : "=r"(a) : "l"(p));
    return a;
}
#define LDSM_X4(r0, r1, r2, r3, addr) \
    asm volatile("ldmatrix.sync.aligned.m8n8.x4.shared.b16 {%0,%1,%2,%3}, [%4];" \
                 : "=r"(r0), "=r"(r1), "=r"(r2), "=r"(r3) : "r"(addr))
__device__ __forceinline__ void mma_bf16(float* c, const u32* a, u32 b0, u32 b1) {
    asm volatile(
        "mma.sync.aligned.m16n8k16.row.col.f32.bf16.bf16.f32 "
        "{%0,%1,%2,%3}, {%4,%5,%6,%7}, {%8,%9}, {%0,%1,%2,%3};"
        : "+f"(c[0]), "+f"(c[1]), "+f"(c[2]), "+f"(c[3])
        : "r"(a[0]), "r"(a[1]), "r"(a[2]), "r"(a[3]), "r"(b0), "r"(b1));
}

// ---------------------------------------------------------------------------
// prep: B[n][k] = Wc[k][n] (n<64: in-path, n>=64: out-path), split to bf16
// hi/lo, written into padded global images. Also combined biases.
// ---------------------------------------------------------------------------
__global__ void prep_kernel(const float* __restrict__ Wmi, const float* __restrict__ Wmo,
                            const float* __restrict__ Wsh,
                            const float* __restrict__ bmi, const float* __restrict__ bmo,
                            const float* __restrict__ bsi, const float* __restrict__ bso) {
    int i = blockIdx.x * blockDim.x + threadIdx.x;
    if (i < 128 * 128) {
        int n = i >> 7, k = i & 127;
        float w;
        if (n < 64) w = Wmi[k * 64 + n] + Wsh[k * 64 + n];
        else        w = Wmo[k * 64 + (n - 64)] + Wsh[k * 64 + (n - 64)];
        __nv_bfloat16 hb = __float2bfloat16(w);
        __nv_bfloat16 lb = __float2bfloat16(w - __bfloat162float(hb));
        int off = n * TSTRIDE + k * 2;
        *(__nv_bfloat16*)(g_Bhi + off) = hb;
        *(__nv_bfloat16*)(g_Blo + off) = lb;
    }
    if (i < 64) {
        g_bc[i]      = bmi[i] + bsi[i];
        g_bc[64 + i] = bmo[i] + bso[i];
    }
}

// ---------------------------------------------------------------------------
// CSR offsets for BOTH sorted target lists: off[t] = first e with tgt[e] >= t.
// ---------------------------------------------------------------------------
__global__ void offsets_kernel(const int* __restrict__ tgt_in,  int Ein,
                               const int* __restrict__ tgt_out, int Eout, int N) {
    int e = blockIdx.x * blockDim.x + threadIdx.x;
    if (e <= Ein) {
        int cur  = (e < Ein) ? tgt_in[e]     : N;
        int prev = (e > 0)   ? tgt_in[e - 1] : -1;
        for (int t = prev + 1; t <= cur; ++t) g_off_in[t] = e;
    }
    if (e <= Eout) {
        int cur  = (e < Eout) ? tgt_out[e]     : N;
        int prev = (e > 0)    ? tgt_out[e - 1] : -1;
        for (int t = prev + 1; t <= cur; ++t) g_off_out[t] = e;
    }
}

// ---------------------------------------------------------------------------
// HMMA GEMM: H(128x128 tile) = Xhi@Bhi^T-ish via mma.sync m16n8k16 bf16.
// SMEM: Ahi | Alo | Bhi | Blo, each 128x136 bf16 (34816 B) = 139264 B total.
// 8 warps: wr = wid&3 (rows wr*32..+32), wc = wid>>2 (cols wc*64..+64).
// ---------------------------------------------------------------------------
#define SA_HI 0
#define SA_LO TILE_BYTES
#define SB_HI (2 * TILE_BYTES)
#define SB_LO (3 * TILE_BYTES)
#define GEMM_SMEM (4 * TILE_BYTES)    // 139264

__global__ __launch_bounds__(256, 1) void gemm_kernel(const float* __restrict__ X, int N) {
    extern __shared__ __align__(16) char smem[];
    u32 sb = smem_u32(smem);
    int tid = threadIdx.x;
    int wid = tid >> 5;
    int lane = tid & 31;
    int node0 = blockIdx.x * 128;

    // copy pre-split B images (L2-hot after first wave)
    {
        const uint4* bh = (const uint4*)g_Bhi;
        const uint4* bl = (const uint4*)g_Blo;
        uint4* dh = (uint4*)(smem + SB_HI);
        uint4* dl = (uint4*)(smem + SB_LO);
        #pragma unroll
        for (int i = tid; i < TILE_BYTES / 16; i += 256) {
            dh[i] = __ldg(&bh[i]); dl[i] = __ldg(&bl[i]);
        }
    }

    // load X rows, split to bf16 hi/lo, store padded. 2 threads per row.
    {
        int r = tid >> 1, h = tid & 1;
        int n = node0 + r;
        const float4* xrow = (const float4*)(X + (size_t)n * 128);
        char* ahp = smem + SA_HI + r * TSTRIDE;
        char* alp = smem + SA_LO + r * TSTRIDE;
        #pragma unroll
        for (int kk = 0; kk < 16; ++kk) {
            int k4 = h * 16 + kk;             // float4 index; k = 4*k4
            float4 v = (n < N) ? __ldg(&xrow[k4]) : make_float4(0.f, 0.f, 0.f, 0.f);
            __nv_bfloat16 h0 = __float2bfloat16(v.x);
            __nv_bfloat16 h1 = __float2bfloat16(v.y);
            __nv_bfloat16 h2 = __float2bfloat16(v.z);
            __nv_bfloat16 h3 = __float2bfloat16(v.w);
            u32 hw0 = (u32)__bfloat16_as_ushort(h0) | ((u32)__bfloat16_as_ushort(h1) << 16);
            u32 hw1 = (u32)__bfloat16_as_ushort(h2) | ((u32)__bfloat16_as_ushort(h3) << 16);
            __nv_bfloat16 l0 = __float2bfloat16(v.x - __bfloat162float(h0));
            __nv_bfloat16 l1 = __float2bfloat16(v.y - __bfloat162float(h1));
            __nv_bfloat16 l2 = __float2bfloat16(v.z - __bfloat162float(h2));
            __nv_bfloat16 l3 = __float2bfloat16(v.w - __bfloat162float(h3));
            u32 lw0 = (u32)__bfloat16_as_ushort(l0) | ((u32)__bfloat16_as_ushort(l1) << 16);
            u32 lw1 = (u32)__bfloat16_as_ushort(l2) | ((u32)__bfloat16_as_ushort(l3) << 16);
            *(u64*)(ahp + k4 * 8) = (u64)hw0 | ((u64)hw1 << 32);
            *(u64*)(alp + k4 * 8) = (u64)lw0 | ((u64)lw1 << 32);
        }
    }
    __syncthreads();

    int wr = wid & 3;      // row group: rows wr*32..wr*32+31
    int wc = wid >> 2;     // col group: cols wc*64..wc*64+63

    // ldmatrix lane base addresses
    // A (m16k16, x4): row = m0 + (lane&15), kbyte = 16*(lane>>4)
    u32 aHi[2], aLo[2];
    #pragma unroll
    for (int mt = 0; mt < 2; ++mt) {
        int row = wr * 32 + mt * 16 + (lane & 15);
        int kb = 16 * (lane >> 4);
        aHi[mt] = sb + SA_HI + row * TSTRIDE + kb;
        aLo[mt] = sb + SA_LO + row * TSTRIDE + kb;
    }
    // B (two n8k16 tiles per x4): n = n0 + p*16 + ((lane>>4)<<3) + (lane&7),
    // kbyte = 16*((lane>>3)&1)
    u32 bHi[4], bLo[4];
    #pragma unroll
    for (int p = 0; p < 4; ++p) {
        int nrow = wc * 64 + p * 16 + ((lane >> 4) << 3) + (lane & 7);
        int kb = 16 * ((lane >> 3) & 1);
        bHi[p] = sb + SB_HI + nrow * TSTRIDE + kb;
        bLo[p] = sb + SB_LO + nrow * TSTRIDE + kb;
    }

    float c[2][8][4];
    #pragma unroll
    for (int mt = 0; mt < 2; ++mt)
        #pragma unroll
        for (int nt = 0; nt < 8; ++nt)
            #pragma unroll
            for (int q = 0; q < 4; ++q) c[mt][nt][q] = 0.f;

    #pragma unroll
    for (int ks = 0; ks < 8; ++ks) {
        int kb = ks * 32;
        u32 ah[2][4], al[2][4];
        #pragma unroll
        for (int mt = 0; mt < 2; ++mt) {
            LDSM_X4(ah[mt][0], ah[mt][1], ah[mt][2], ah[mt][3], aHi[mt] + kb);
            LDSM_X4(al[mt][0], al[mt][1], al[mt][2], al[mt][3], aLo[mt] + kb);
        }
        u32 bh[4][4], bl[4][4];
        #pragma unroll
        for (int p = 0; p < 4; ++p) {
            LDSM_X4(bh[p][0], bh[p][1], bh[p][2], bh[p][3], bHi[p] + kb);
            LDSM_X4(bl[p][0], bl[p][1], bl[p][2], bl[p][3], bLo[p] + kb);
        }
        #pragma unroll
        for (int mt = 0; mt < 2; ++mt)
            #pragma unroll
            for (int p = 0; p < 4; ++p) {
                mma_bf16(c[mt][2 * p],     ah[mt], bh[p][0], bh[p][1]);
                mma_bf16(c[mt][2 * p + 1], ah[mt], bh[p][2], bh[p][3]);
                mma_bf16(c[mt][2 * p],     ah[mt], bl[p][0], bl[p][1]);
                mma_bf16(c[mt][2 * p + 1], ah[mt], bl[p][2], bl[p][3]);
                mma_bf16(c[mt][2 * p],     al[mt], bh[p][0], bh[p][1]);
                mma_bf16(c[mt][2 * p + 1], al[mt], bh[p][2], bh[p][3]);
            }
    }

    // epilogue: c fragment lane layout: d0,d1 -> row lane/4, cols (lane%4)*2;
    // d2,d3 -> row lane/4 + 8.
    #pragma unroll
    for (int mt = 0; mt < 2; ++mt) {
        int row0 = node0 + wr * 32 + mt * 16 + (lane >> 2);
        #pragma unroll
        for (int hf = 0; hf < 2; ++hf) {
            int row = row0 + hf * 8;
            if (row < N) {
                float* Hp = g_H + (size_t)row * 128 + wc * 64 + (lane & 3) * 2;
                #pragma unroll
                for (int nt = 0; nt < 8; ++nt) {
                    float2 v = make_float2(c[mt][nt][hf * 2], c[mt][nt][hf * 2 + 1]);
                    *(float2*)(Hp + nt * 8) = v;
                }
            }
        }
    }
}

// ---------------------------------------------------------------------------
// Pull gather: ONE WARP per target node. Lane l owns channel pair (2l, 2l+1)
// of each path. LDG.64 H reads (256B/warp/edge, L2-resident), f32x2 acc.
// ---------------------------------------------------------------------------
__global__ __launch_bounds__(256) void gather_kernel(
        const int* __restrict__ src_in,  const float* __restrict__ w_in,
        const int* __restrict__ src_out, const float* __restrict__ w_out,
        const float* __restrict__ Cin,   const float* __restrict__ Cout,
        float* __restrict__ out, int N) {
    int gid = blockIdx.x * blockDim.x + threadIdx.x;
    int t = gid >> 5;
    if (t >= N) return;
    int l2 = (gid & 31) * 2;

    u64 acc_in = 0ull;
    {
        int lo = g_off_in[t], hi = g_off_in[t + 1];
        const u64* Hp = (const u64*)(g_H + l2);
        int e = lo;
        for (; e + 3 < hi; e += 4) {
            int   s0 = __ldg(&src_in[e]),     s1 = __ldg(&src_in[e + 1]);
            int   s2 = __ldg(&src_in[e + 2]), s3 = __ldg(&src_in[e + 3]);
            float f0 = __ldg(&w_in[e]),       f1 = __ldg(&w_in[e + 1]);
            float f2 = __ldg(&w_in[e + 2]),   f3 = __ldg(&w_in[e + 3]);
            u64 h0 = __ldg(&Hp[(size_t)s0 * 64]);
            u64 h1 = __ldg(&Hp[(size_t)s1 * 64]);
            u64 h2 = __ldg(&Hp[(size_t)s2 * 64]);
            u64 h3 = __ldg(&Hp[(size_t)s3 * 64]);
            ffma2(acc_in, pack2(f0, f0), h0);
            ffma2(acc_in, pack2(f1, f1), h1);
            ffma2(acc_in, pack2(f2, f2), h2);
            ffma2(acc_in, pack2(f3, f3), h3);
        }
        for (; e < hi; ++e) {
            float f = __ldg(&w_in[e]);
            u64 h = __ldg(&Hp[(size_t)__ldg(&src_in[e]) * 64]);
            ffma2(acc_in, pack2(f, f), h);
        }
    }

    u64 acc_out = 0ull;
    {
        int lo = g_off_out[t], hi = g_off_out[t + 1];
        const u64* Hp = (const u64*)(g_H + 64 + l2);
        int e = lo;
        for (; e + 3 < hi; e += 4) {
            int   s0 = __ldg(&src_out[e]),     s1 = __ldg(&src_out[e + 1]);
            int   s2 = __ldg(&src_out[e + 2]), s3 = __ldg(&src_out[e + 3]);
            float f0 = __ldg(&w_out[e]),       f1 = __ldg(&w_out[e + 1]);
            float f2 = __ldg(&w_out[e + 2]),   f3 = __ldg(&w_out[e + 3]);
            u64 h0 = __ldg(&Hp[(size_t)s0 * 64]);
            u64 h1 = __ldg(&Hp[(size_t)s1 * 64]);
            u64 h2 = __ldg(&Hp[(size_t)s2 * 64]);
            u64 h3 = __ldg(&Hp[(size_t)s3 * 64]);
            ffma2(acc_out, pack2(f0, f0), h0);
            ffma2(acc_out, pack2(f1, f1), h1);
            ffma2(acc_out, pack2(f2, f2), h2);
            ffma2(acc_out, pack2(f3, f3), h3);
        }
        for (; e < hi; ++e) {
            float f = __ldg(&w_out[e]);
            u64 h = __ldg(&Hp[(size_t)__ldg(&src_out[e]) * 64]);
            ffma2(acc_out, pack2(f, f), h);
        }
    }

    float ai, aj, oi, oj;
    unpack2(ai, aj, acc_in);
    unpack2(oi, oj, acc_out);
    float ci = __ldg(&Cin[t]), co = __ldg(&Cout[t]);
    float2 r;
    r.x = ci * (ai + g_bc[l2])     + co * (oi + g_bc[64 + l2]);
    r.y = ci * (aj + g_bc[l2 + 1]) + co * (oj + g_bc[65 + l2]);
    *(float2*)&out[(size_t)t * 64 + l2] = r;
}

// ---------------------------------------------------------------------------
extern "C" void kernel_launch(void* const* d_in, const int* in_sizes, int n_in,
                              void* d_out, int out_size) {
    const float* x    = (const float*)d_in[0];
    const float* Wmi  = (const float*)d_in[1];
    const float* Wmo  = (const float*)d_in[2];
    const float* Wsh  = (const float*)d_in[3];
    const float* bmi  = (const float*)d_in[4];
    const float* bmo  = (const float*)d_in[5];
    const float* bsi  = (const float*)d_in[6];
    const float* bso  = (const float*)d_in[7];
    const float* Cin  = (const float*)d_in[8];
    const float* Cout = (const float*)d_in[9];
    const int*   ei_in  = (const int*)d_in[10];
    const float* ew_in  = (const float*)d_in[11];
    const int*   ei_out = (const int*)d_in[12];
    const float* ew_out = (const float*)d_in[13];

    int N    = in_sizes[0] / 128;
    int Ein  = in_sizes[10] / 2;
    int Eout = in_sizes[12] / 2;
    float* out = (float*)d_out;

    int Emax = (Ein > Eout ? Ein : Eout);

    cudaFuncSetAttribute(gemm_kernel, cudaFuncAttributeMaxDynamicSharedMemorySize,
                         GEMM_SMEM);

    prep_kernel<<<64, 256>>>(Wmi, Wmo, Wsh, bmi, bmo, bsi, bso);
    offsets_kernel<<<(Emax + 1 + 255) / 256, 256>>>(ei_in + Ein, Ein,
                                                    ei_out + Eout, Eout, N);
    gemm_kernel<<<(N + 127) / 128, 256, GEMM_SMEM>>>(x, N);
    gather_kernel<<<((size_t)N * 32 + 255) / 256, 256>>>(
        ei_in, ew_in, ei_out, ew_out, Cin, Cout, out, N);
}

// round 11
// speedup vs baseline: 2.2125x; 1.0197x over previous
#include <cuda_runtime.h>
#include <cuda_bf16.h>
#include <cuda_fp16.h>
#include <cstdint>

// ---------------------------------------------------------------------------
// DirectGCNLayer on GB300 (sm_103a) — R10
//
//   Wc_in  = W_main_in  + W_shared ;  Wc_out = W_main_out + W_shared
//   H      = X @ [Wc_in | Wc_out]              (N x 128, stored FP16)
//   out[t] = C_in[t] *(sum_in  w*H[src][0:64]   + bc_in)
//          + C_out[t]*(sum_out w*H[src][64:128] + bc_out)
//
// GEMM: mma.sync m16n8k16 bf16 (HMMA; plain-sm_103 PTX — tcgen05 is rejected
// by this harness's ptxas target), bf16 hi/lo split, 3 passes, fp32 accum.
// R10: H stored as fp16 -> gather reads 1 L2 line per edge (128B) instead of
// 2; fp32 accumulation keeps output rel_err ~3e-4 << 1e-3.
// Gather: warp-per-node pull (atomic-free, CSR from sorted targets).
// ---------------------------------------------------------------------------

#define MAX_N 100000

typedef unsigned long long u64;
typedef unsigned int u32;

// padded bf16 tile: 128 rows x 136 cols (272 B row stride)
#define TSTRIDE 272
#define TILE_BYTES (128 * TSTRIDE)     // 34816

__device__ __half g_H2[(size_t)MAX_N * 128];        // 25.6 MB, fp16 H
__device__ float g_bc[128];                         // combined biases [in|out]
__device__ int   g_off_in[MAX_N + 1];
__device__ int   g_off_out[MAX_N + 1];
__device__ __align__(16) unsigned char g_Bhi[TILE_BYTES]; // B=Wc^T bf16 hi, padded
__device__ __align__(16) unsigned char g_Blo[TILE_BYTES]; // B=Wc^T bf16 lo, padded

// ---- helpers ---------------------------------------------------------------
__device__ __forceinline__ u32 smem_u32(const void* p) {
    u32 a; asm("{ .reg .u64 t; cvta.to.shared.u64 t, %1; cvt.u32.u64 %0, t; }"
               : "=r"(a) : "l"(p));
    return a;
}
#define LDSM_X4(r0, r1, r2, r3, addr) \
    asm volatile("ldmatrix.sync.aligned.m8n8.x4.shared.b16 {%0,%1,%2,%3}, [%4];" \
                 : "=r"(r0), "=r"(r1), "=r"(r2), "=r"(r3) : "r"(addr))
__device__ __forceinline__ void mma_bf16(float* c, const u32* a, u32 b0, u32 b1) {
    asm volatile(
        "mma.sync.aligned.m16n8k16.row.col.f32.bf16.bf16.f32 "
        "{%0,%1,%2,%3}, {%4,%5,%6,%7}, {%8,%9}, {%0,%1,%2,%3};"
        : "+f"(c[0]), "+f"(c[1]), "+f"(c[2]), "+f"(c[3])
        : "r"(a[0]), "r"(a[1]), "r"(a[2]), "r"(a[3]), "r"(b0), "r"(b1));
}

// ---------------------------------------------------------------------------
// prep: B[n][k] = Wc[k][n] (n<64: in-path, n>=64: out-path), split to bf16
// hi/lo, written into padded global images. Also combined biases.
// ---------------------------------------------------------------------------
__global__ void prep_kernel(const float* __restrict__ Wmi, const float* __restrict__ Wmo,
                            const float* __restrict__ Wsh,
                            const float* __restrict__ bmi, const float* __restrict__ bmo,
                            const float* __restrict__ bsi, const float* __restrict__ bso) {
    int i = blockIdx.x * blockDim.x + threadIdx.x;
    if (i < 128 * 128) {
        int n = i >> 7, k = i & 127;
        float w;
        if (n < 64) w = Wmi[k * 64 + n] + Wsh[k * 64 + n];
        else        w = Wmo[k * 64 + (n - 64)] + Wsh[k * 64 + (n - 64)];
        __nv_bfloat16 hb = __float2bfloat16(w);
        __nv_bfloat16 lb = __float2bfloat16(w - __bfloat162float(hb));
        int off = n * TSTRIDE + k * 2;
        *(__nv_bfloat16*)(g_Bhi + off) = hb;
        *(__nv_bfloat16*)(g_Blo + off) = lb;
    }
    if (i < 64) {
        g_bc[i]      = bmi[i] + bsi[i];
        g_bc[64 + i] = bmo[i] + bso[i];
    }
}

// ---------------------------------------------------------------------------
// CSR offsets for BOTH sorted target lists: off[t] = first e with tgt[e] >= t.
// ---------------------------------------------------------------------------
__global__ void offsets_kernel(const int* __restrict__ tgt_in,  int Ein,
                               const int* __restrict__ tgt_out, int Eout, int N) {
    int e = blockIdx.x * blockDim.x + threadIdx.x;
    if (e <= Ein) {
        int cur  = (e < Ein) ? tgt_in[e]     : N;
        int prev = (e > 0)   ? tgt_in[e - 1] : -1;
        for (int t = prev + 1; t <= cur; ++t) g_off_in[t] = e;
    }
    if (e <= Eout) {
        int cur  = (e < Eout) ? tgt_out[e]     : N;
        int prev = (e > 0)    ? tgt_out[e - 1] : -1;
        for (int t = prev + 1; t <= cur; ++t) g_off_out[t] = e;
    }
}

// ---------------------------------------------------------------------------
// HMMA GEMM: 128x128x128 tile/CTA, 8 warps (4 row x 2 col).
// SMEM: Ahi | Alo | Bhi | Blo, each 128x136 bf16 (34816 B) = 139264 B total.
// ---------------------------------------------------------------------------
#define SA_HI 0
#define SA_LO TILE_BYTES
#define SB_HI (2 * TILE_BYTES)
#define SB_LO (3 * TILE_BYTES)
#define GEMM_SMEM (4 * TILE_BYTES)    // 139264

__global__ __launch_bounds__(256, 1) void gemm_kernel(const float* __restrict__ X, int N) {
    extern __shared__ __align__(16) char smem[];
    u32 sb = smem_u32(smem);
    int tid = threadIdx.x;
    int wid = tid >> 5;
    int lane = tid & 31;
    int node0 = blockIdx.x * 128;

    // copy pre-split B images (L2-hot after first wave)
    {
        const uint4* bh = (const uint4*)g_Bhi;
        const uint4* bl = (const uint4*)g_Blo;
        uint4* dh = (uint4*)(smem + SB_HI);
        uint4* dl = (uint4*)(smem + SB_LO);
        #pragma unroll
        for (int i = tid; i < TILE_BYTES / 16; i += 256) {
            dh[i] = __ldg(&bh[i]); dl[i] = __ldg(&bl[i]);
        }
    }

    // load X rows, split to bf16 hi/lo, store padded. 2 threads per row.
    {
        int r = tid >> 1, h = tid & 1;
        int n = node0 + r;
        const float4* xrow = (const float4*)(X + (size_t)n * 128);
        char* ahp = smem + SA_HI + r * TSTRIDE;
        char* alp = smem + SA_LO + r * TSTRIDE;
        #pragma unroll
        for (int kk = 0; kk < 16; ++kk) {
            int k4 = h * 16 + kk;             // float4 index; k = 4*k4
            float4 v = (n < N) ? __ldg(&xrow[k4]) : make_float4(0.f, 0.f, 0.f, 0.f);
            __nv_bfloat16 h0 = __float2bfloat16(v.x);
            __nv_bfloat16 h1 = __float2bfloat16(v.y);
            __nv_bfloat16 h2 = __float2bfloat16(v.z);
            __nv_bfloat16 h3 = __float2bfloat16(v.w);
            u32 hw0 = (u32)__bfloat16_as_ushort(h0) | ((u32)__bfloat16_as_ushort(h1) << 16);
            u32 hw1 = (u32)__bfloat16_as_ushort(h2) | ((u32)__bfloat16_as_ushort(h3) << 16);
            __nv_bfloat16 l0 = __float2bfloat16(v.x - __bfloat162float(h0));
            __nv_bfloat16 l1 = __float2bfloat16(v.y - __bfloat162float(h1));
            __nv_bfloat16 l2 = __float2bfloat16(v.z - __bfloat162float(h2));
            __nv_bfloat16 l3 = __float2bfloat16(v.w - __bfloat162float(h3));
            u32 lw0 = (u32)__bfloat16_as_ushort(l0) | ((u32)__bfloat16_as_ushort(l1) << 16);
            u32 lw1 = (u32)__bfloat16_as_ushort(l2) | ((u32)__bfloat16_as_ushort(l3) << 16);
            *(u64*)(ahp + k4 * 8) = (u64)hw0 | ((u64)hw1 << 32);
            *(u64*)(alp + k4 * 8) = (u64)lw0 | ((u64)lw1 << 32);
        }
    }
    __syncthreads();

    int wr = wid & 3;      // row group: rows wr*32..wr*32+31
    int wc = wid >> 2;     // col group: cols wc*64..wc*64+63

    // ldmatrix lane base addresses
    u32 aHi[2], aLo[2];
    #pragma unroll
    for (int mt = 0; mt < 2; ++mt) {
        int row = wr * 32 + mt * 16 + (lane & 15);
        int kb = 16 * (lane >> 4);
        aHi[mt] = sb + SA_HI + row * TSTRIDE + kb;
        aLo[mt] = sb + SA_LO + row * TSTRIDE + kb;
    }
    u32 bHi[4], bLo[4];
    #pragma unroll
    for (int p = 0; p < 4; ++p) {
        int nrow = wc * 64 + p * 16 + ((lane >> 4) << 3) + (lane & 7);
        int kb = 16 * ((lane >> 3) & 1);
        bHi[p] = sb + SB_HI + nrow * TSTRIDE + kb;
        bLo[p] = sb + SB_LO + nrow * TSTRIDE + kb;
    }

    float c[2][8][4];
    #pragma unroll
    for (int mt = 0; mt < 2; ++mt)
        #pragma unroll
        for (int nt = 0; nt < 8; ++nt)
            #pragma unroll
            for (int q = 0; q < 4; ++q) c[mt][nt][q] = 0.f;

    #pragma unroll
    for (int ks = 0; ks < 8; ++ks) {
        int kb = ks * 32;
        u32 ah[2][4], al[2][4];
        #pragma unroll
        for (int mt = 0; mt < 2; ++mt) {
            LDSM_X4(ah[mt][0], ah[mt][1], ah[mt][2], ah[mt][3], aHi[mt] + kb);
            LDSM_X4(al[mt][0], al[mt][1], al[mt][2], al[mt][3], aLo[mt] + kb);
        }
        u32 bh[4][4], bl[4][4];
        #pragma unroll
        for (int p = 0; p < 4; ++p) {
            LDSM_X4(bh[p][0], bh[p][1], bh[p][2], bh[p][3], bHi[p] + kb);
            LDSM_X4(bl[p][0], bl[p][1], bl[p][2], bl[p][3], bLo[p] + kb);
        }
        #pragma unroll
        for (int mt = 0; mt < 2; ++mt)
            #pragma unroll
            for (int p = 0; p < 4; ++p) {
                mma_bf16(c[mt][2 * p],     ah[mt], bh[p][0], bh[p][1]);
                mma_bf16(c[mt][2 * p + 1], ah[mt], bh[p][2], bh[p][3]);
                mma_bf16(c[mt][2 * p],     ah[mt], bl[p][0], bl[p][1]);
                mma_bf16(c[mt][2 * p + 1], ah[mt], bl[p][2], bl[p][3]);
                mma_bf16(c[mt][2 * p],     al[mt], bh[p][0], bh[p][1]);
                mma_bf16(c[mt][2 * p + 1], al[mt], bh[p][2], bh[p][3]);
            }
    }

    // epilogue: fragment layout: d0,d1 -> row lane/4, cols (lane%4)*2;
    // d2,d3 -> row +8. Convert to fp16 pairs; one u32 store per n-tile.
    #pragma unroll
    for (int mt = 0; mt < 2; ++mt) {
        int row0 = node0 + wr * 32 + mt * 16 + (lane >> 2);
        #pragma unroll
        for (int hf = 0; hf < 2; ++hf) {
            int row = row0 + hf * 8;
            if (row < N) {
                u32* Hp = (u32*)g_H2 + (size_t)row * 64 + wc * 32 + (lane & 3);
                #pragma unroll
                for (int nt = 0; nt < 8; ++nt) {
                    __half2 v = __float22half2_rn(
                        make_float2(c[mt][nt][hf * 2], c[mt][nt][hf * 2 + 1]));
                    Hp[nt * 4] = *(u32*)&v;
                }
            }
        }
    }
}

// ---------------------------------------------------------------------------
// Pull gather: ONE WARP per target node. Lane l owns channel pair (2l, 2l+1).
// H rows are fp16: one LDG.32 per lane per edge -> 128 B/warp/edge = ONE L2
// line per path. fp32 accumulation.
// ---------------------------------------------------------------------------
__global__ __launch_bounds__(256) void gather_kernel(
        const int* __restrict__ src_in,  const float* __restrict__ w_in,
        const int* __restrict__ src_out, const float* __restrict__ w_out,
        const float* __restrict__ Cin,   const float* __restrict__ Cout,
        float* __restrict__ out, int N) {
    int gid = blockIdx.x * blockDim.x + threadIdx.x;
    int t = gid >> 5;
    if (t >= N) return;
    int l = gid & 31;                  // u32 index within row half; chans (2l,2l+1)

    float ax = 0.f, ay = 0.f;
    {
        int lo = g_off_in[t], hi = g_off_in[t + 1];
        const u32* Hp = (const u32*)g_H2 + l;      // in-path: row offset 64 u32
        int e = lo;
        for (; e + 3 < hi; e += 4) {
            int   s0 = __ldg(&src_in[e]),     s1 = __ldg(&src_in[e + 1]);
            int   s2 = __ldg(&src_in[e + 2]), s3 = __ldg(&src_in[e + 3]);
            float f0 = __ldg(&w_in[e]),       f1 = __ldg(&w_in[e + 1]);
            float f2 = __ldg(&w_in[e + 2]),   f3 = __ldg(&w_in[e + 3]);
            u32 h0 = __ldg(&Hp[(size_t)s0 * 64]);
            u32 h1 = __ldg(&Hp[(size_t)s1 * 64]);
            u32 h2 = __ldg(&Hp[(size_t)s2 * 64]);
            u32 h3 = __ldg(&Hp[(size_t)s3 * 64]);
            float2 v0 = __half22float2(*(__half2*)&h0);
            float2 v1 = __half22float2(*(__half2*)&h1);
            float2 v2 = __half22float2(*(__half2*)&h2);
            float2 v3 = __half22float2(*(__half2*)&h3);
            ax += f0 * v0.x; ay += f0 * v0.y;
            ax += f1 * v1.x; ay += f1 * v1.y;
            ax += f2 * v2.x; ay += f2 * v2.y;
            ax += f3 * v3.x; ay += f3 * v3.y;
        }
        for (; e < hi; ++e) {
            float f = __ldg(&w_in[e]);
            u32 h = __ldg(&Hp[(size_t)__ldg(&src_in[e]) * 64]);
            float2 v = __half22float2(*(__half2*)&h);
            ax += f * v.x; ay += f * v.y;
        }
    }

    float ox = 0.f, oy = 0.f;
    {
        int lo = g_off_out[t], hi = g_off_out[t + 1];
        const u32* Hp = (const u32*)g_H2 + 32 + l; // out-path half of the row
        int e = lo;
        for (; e + 3 < hi; e += 4) {
            int   s0 = __ldg(&src_out[e]),     s1 = __ldg(&src_out[e + 1]);
            int   s2 = __ldg(&src_out[e + 2]), s3 = __ldg(&src_out[e + 3]);
            float f0 = __ldg(&w_out[e]),       f1 = __ldg(&w_out[e + 1]);
            float f2 = __ldg(&w_out[e + 2]),   f3 = __ldg(&w_out[e + 3]);
            u32 h0 = __ldg(&Hp[(size_t)s0 * 64]);
            u32 h1 = __ldg(&Hp[(size_t)s1 * 64]);
            u32 h2 = __ldg(&Hp[(size_t)s2 * 64]);
            u32 h3 = __ldg(&Hp[(size_t)s3 * 64]);
            float2 v0 = __half22float2(*(__half2*)&h0);
            float2 v1 = __half22float2(*(__half2*)&h1);
            float2 v2 = __half22float2(*(__half2*)&h2);
            float2 v3 = __half22float2(*(__half2*)&h3);
            ox += f0 * v0.x; oy += f0 * v0.y;
            ox += f1 * v1.x; oy += f1 * v1.y;
            ox += f2 * v2.x; oy += f2 * v2.y;
            ox += f3 * v3.x; oy += f3 * v3.y;
        }
        for (; e < hi; ++e) {
            float f = __ldg(&w_out[e]);
            u32 h = __ldg(&Hp[(size_t)__ldg(&src_out[e]) * 64]);
            float2 v = __half22float2(*(__half2*)&h);
            ox += f * v.x; oy += f * v.y;
        }
    }

    int l2 = l * 2;
    float ci = __ldg(&Cin[t]), co = __ldg(&Cout[t]);
    float2 r;
    r.x = ci * (ax + g_bc[l2])     + co * (ox + g_bc[64 + l2]);
    r.y = ci * (ay + g_bc[l2 + 1]) + co * (oy + g_bc[65 + l2]);
    *(float2*)&out[(size_t)t * 64 + l2] = r;
}

// ---------------------------------------------------------------------------
extern "C" void kernel_launch(void* const* d_in, const int* in_sizes, int n_in,
                              void* d_out, int out_size) {
    const float* x    = (const float*)d_in[0];
    const float* Wmi  = (const float*)d_in[1];
    const float* Wmo  = (const float*)d_in[2];
    const float* Wsh  = (const float*)d_in[3];
    const float* bmi  = (const float*)d_in[4];
    const float* bmo  = (const float*)d_in[5];
    const float* bsi  = (const float*)d_in[6];
    const float* bso  = (const float*)d_in[7];
    const float* Cin  = (const float*)d_in[8];
    const float* Cout = (const float*)d_in[9];
    const int*   ei_in  = (const int*)d_in[10];
    const float* ew_in  = (const float*)d_in[11];
    const int*   ei_out = (const int*)d_in[12];
    const float* ew_out = (const float*)d_in[13];

    int N    = in_sizes[0] / 128;
    int Ein  = in_sizes[10] / 2;
    int Eout = in_sizes[12] / 2;
    float* out = (float*)d_out;

    int Emax = (Ein > Eout ? Ein : Eout);

    cudaFuncSetAttribute(gemm_kernel, cudaFuncAttributeMaxDynamicSharedMemorySize,
                         GEMM_SMEM);

    prep_kernel<<<64, 256>>>(Wmi, Wmo, Wsh, bmi, bmo, bsi, bso);
    offsets_kernel<<<(Emax + 1 + 255) / 256, 256>>>(ei_in + Ein, Ein,
                                                    ei_out + Eout, Eout, N);
    gemm_kernel<<<(N + 127) / 128, 256, GEMM_SMEM>>>(x, N);
    gather_kernel<<<((size_t)N * 32 + 255) / 256, 256>>>(
        ei_in, ew_in, ei_out, ew_out, Cin, Cout, out, N);
}